// round 7
// baseline (speedup 1.0000x reference)
#include <cuda_runtime.h>
#include <math.h>
#include <stdint.h>

#define TT 512
#define BB 64
#define HH 512
#define GRID 128
#define NTHREADS 512
#define AST 516   // A staging row stride in floats (16B-aligned, 2-way-opt banks)

// ---------------- device globals (no allocation allowed) ----------------
__device__ unsigned long long g_arrive;
__device__ unsigned long long g_release;
__device__ float g_s[5][BB * HH];            // states s0..s4 (full rows)
__device__ float g_wt0[1024 * 1024];         // W0^T  [col][k]   (4 MB)
__device__ float g_wts[8][1024 * 512];       // Ws^T  [i][col][k] (16 MB)

// ---- smem layout (floats) ----
#define OFF_A   0
#define SZ_A    (BB * AST)                   // 33,024 fl = 132,096 B
#define OFF_CH  (SZ_A)                       // 2*512 fl
#define OFF_SL  (OFF_CH + 1024)              // 9*256 fl
#define SMEM_FLOATS (OFF_SL + 9 * 256)
#define SMEM_TOTAL  (SMEM_FLOATS * 4)        // 145,408 B

__device__ __forceinline__ void fma2(unsigned long long &d, unsigned long long a,
                                     unsigned long long b) {
    asm("fma.rn.f32x2 %0, %1, %2, %0;" : "+l"(d) : "l"(a), "l"(b));
}

// Monotonic grid barrier: safe across graph replays (counters never reset).
// 128 CTAs co-resident (1 CTA/SM), so spinning is safe.
__device__ __forceinline__ void grid_bar(int tid) {
    __syncthreads();
    if (tid == 0) {
        __threadfence();
        unsigned long long a = atomicAdd(&g_arrive, 1ULL) + 1ULL;
        unsigned long long phase = (a + (GRID - 1)) / GRID;
        if (a == phase * (unsigned long long)GRID) {
            asm volatile("st.release.gpu.u64 [%0], %1;"
                         :: "l"(&g_release), "l"(phase) : "memory");
        } else {
            unsigned long long v;
            do {
                asm volatile("ld.acquire.gpu.u64 %0, [%1];"
                             : "=l"(v) : "l"(&g_release) : "memory");
            } while (v < phase);
        }
        __threadfence();
    }
    __syncthreads();
}

// Stage one half (64 rows x 256 k) of a [64x512] row-major source into smem A.
__device__ __forceinline__ void stage_half(float* dstA, const float* src,
                                           int khalf, int tid) {
    const float* s = src + khalf * 256;
    float* d = dstA + khalf * 256;
#pragma unroll
    for (int q = 0; q < 8; ++q) {
        int f = tid + q * NTHREADS;        // 0..4095 float4s
        int row = f >> 6, k4 = f & 63;
        const float* g = s + row * 512 + k4 * 4;
        float* dd = d + row * AST + k4 * 4;
        unsigned int da = (unsigned int)__cvta_generic_to_shared(dd);
        asm volatile("cp.async.cg.shared.global [%0], [%1], 16;" :: "r"(da), "l"(g));
    }
}

// FMA over one 256-k half. A from smem; W streamed from global (transposed).
// wcolp = per-thread W base = wt + (ci*512 + colbase)*wstride  (+ phase k off).
template <int NSETS>
__device__ __forceinline__ void gemm_half(const float* __restrict__ as,
        const float* __restrict__ wcolp, long long wstride,
        int khalf, int wk, int ri, unsigned long long (&acc)[4][4]) {
    constexpr int KW = (NSETS == 2) ? 32 : 16;   // k's per warp per half
    constexpr int T4 = KW / 4;
    const int kl0 = khalf * 256 + wk * KW;

    ulonglong2 wcur[4], wnxt[4];
#pragma unroll
    for (int j = 0; j < 4; ++j)
        wcur[j] = __ldg(reinterpret_cast<const ulonglong2*>(
            wcolp + j * wstride + kl0));
#pragma unroll
    for (int t4 = 0; t4 < T4; ++t4) {
        const int kl = kl0 + t4 * 4;
        ulonglong2 a2[4];
#pragma unroll
        for (int i = 0; i < 4; ++i)
            a2[i] = *reinterpret_cast<const ulonglong2*>(
                as + (ri + 16 * i) * AST + kl);
        if (t4 + 1 < T4) {
#pragma unroll
            for (int j = 0; j < 4; ++j)
                wnxt[j] = __ldg(reinterpret_cast<const ulonglong2*>(
                    wcolp + j * wstride + kl + 4));
        }
#pragma unroll
        for (int j = 0; j < 4; ++j)
#pragma unroll
            for (int i = 0; i < 4; ++i) {
                fma2(acc[i][j], a2[i].x, wcur[j].x);
                fma2(acc[i][j], a2[i].y, wcur[j].y);
            }
#pragma unroll
        for (int j = 0; j < 4; ++j) wcur[j] = wnxt[j];
    }
}

// One DAG level. NPH phases of K=512 accumulate (L0 uses 2: x then h).
// NSETS==2: warps 0-7 set0, 8-15 set1. Epilogue: reduce + gate + store.
template <int NSETS, int NPH>
__device__ __forceinline__ void do_level(float* smem, int tid,
        const float* srcA0, const float* srcA1,
        const float* wt0, const float* wt1, long long wstride, int colbase,
        int act0, int act1, int pred0, int pred1, int st0, int st1,
        float* gd0, float* gd1, const float* __restrict__ hprevRow) {
    float* as = smem + OFF_A;
    float* ch = smem + OFF_CH;
    float* sl = smem + OFF_SL;

    const int warp = tid >> 5, lane = tid & 31;
    const int ri = lane & 15, ci = lane >> 4;
    const int wk = (NSETS == 2) ? (warp & 7) : warp;
    const float* wt = (NSETS == 2 && warp >= 8) ? wt1 : wt0;

    unsigned long long acc[4][4];
#pragma unroll
    for (int i = 0; i < 4; ++i)
#pragma unroll
        for (int j = 0; j < 4; ++j) acc[i][j] = 0ULL;

#pragma unroll
    for (int ph = 0; ph < NPH; ++ph) {
        const float* sa = ph ? srcA1 : srcA0;
        const float* wcolp = wt + (long long)(ci * 512 + colbase) * wstride
                             + ph * 512;     // phase offset in k
        stage_half(as, sa, 0, tid);
        asm volatile("cp.async.commit_group;");
        stage_half(as, sa, 1, tid);
        asm volatile("cp.async.commit_group;");
        asm volatile("cp.async.wait_group 1;");
        __syncthreads();
        gemm_half<NSETS>(as, wcolp, wstride, 0, wk, ri, acc);
        asm volatile("cp.async.wait_group 0;");
        __syncthreads();
        gemm_half<NSETS>(as, wcolp, wstride, 1, wk, ri, acc);
        __syncthreads();   // A dead: safe to restage (next phase) or overlay
    }

    // --- dump per-warp K-partials into the (dead) A region ---
    float* bufred = as;
#pragma unroll
    for (int i = 0; i < 4; ++i)
#pragma unroll
        for (int j = 0; j < 4; ++j) {
            float2 f = *reinterpret_cast<float2*>(&acc[i][j]);
            bufred[warp * 512 + (ri + 16 * i) * 8 + (4 * ci + j)] = f.x + f.y;
        }
    __syncthreads();

    // --- cross-warp reduce, both sets concurrently ---
    for (int idx = tid; idx < 512 * NSETS; idx += NTHREADS) {
        int set = idx >> 9, o = idx & 511;
        int wbase = (NSETS == 2) ? (set * 8) : 0;
        constexpr int WCNT = (NSETS == 2) ? 8 : 16;
        float v = 0.f;
#pragma unroll
        for (int w = 0; w < WCNT; ++w) v += bufred[(wbase + w) * 512 + o];
        ch[set * 512 + o] = v;
    }
    __syncthreads();

    // --- gated elementwise ---
    for (int idx = tid; idx < 256 * NSETS; idx += NTHREADS) {
        int s = idx >> 8, r = idx & 255;
        int b = r >> 2, pj = r & 3;
        int act = (s == 0) ? act0 : act1;
        int pred = (s == 0) ? pred0 : pred1;
        int st = (s == 0) ? st0 : st1;
        float* gd = (s == 0) ? gd0 : gd1;
        float gv = ch[s * 512 + b * 8 + pj];
        float cv = ch[s * 512 + b * 8 + 4 + pj];
        float gate = 1.f / (1.f + expf(-gv));
        float hh;
        if (act == 0)      hh = tanhf(cv);
        else if (act == 1) hh = fmaxf(cv, 0.f);
        else if (act == 2) hh = 1.f / (1.f + expf(-cv));
        else               hh = cv;
        float sp = (pred < 0) ? hprevRow[b * 512 + colbase + pj]
                              : sl[pred * 256 + b * 4 + pj];
        float sv = fmaf(gate, hh - sp, sp);
        sl[st * 256 + b * 4 + pj] = sv;
        if (gd) gd[b * 512 + colbase + pj] = sv;
    }
    __syncthreads();
}

// ---------- prep kernel: transpose W0 (1024x1024) and Ws (8x 512x1024) ----------
__global__ void wt_transpose_kernel(const float* __restrict__ W0,
                                    const float* __restrict__ Ws) {
    __shared__ float tile[32][33];
    int z = blockIdx.z;
    const float* src;
    float* dst;
    int R;
    if (z == 0) { src = W0; dst = g_wt0; R = 1024; }
    else        { src = Ws + (size_t)(z - 1) * 512 * 1024; dst = g_wts[z - 1]; R = 512; }
    int rb = blockIdx.y * 32, cb = blockIdx.x * 32;
    if (rb >= R) return;
#pragma unroll
    for (int i = 0; i < 4; ++i) {
        int r = rb + threadIdx.y + i * 8;
        tile[threadIdx.y + i * 8][threadIdx.x] = src[(size_t)r * 1024 + cb + threadIdx.x];
    }
    __syncthreads();
#pragma unroll
    for (int i = 0; i < 4; ++i) {
        int c = cb + threadIdx.y + i * 8;
        dst[(size_t)c * R + rb + threadIdx.x] = tile[threadIdx.x][threadIdx.y + i * 8];
    }
}

__global__ void __launch_bounds__(NTHREADS, 1)
nao_kernel(const float* __restrict__ x, const float* __restrict__ h0,
           float* __restrict__ out, long long out_size) {
    extern __shared__ unsigned char smemRaw[];
    float* smem = reinterpret_cast<float*>(smemRaw);
    float* sl = smem + OFF_SL;
    const int tid = threadIdx.x;
    const int colbase = blockIdx.x * 4;

    for (int t = 0; t < TT; ++t) {
        const float* xt = x + (size_t)t * BB * 512;
        const float* hRow = (t == 0) ? h0 : (out + (size_t)(t - 1) * BB * HH);

        // Level 0: s0 from [x;h] @ W0 (two K=512 accumulate phases)
        do_level<1, 2>(smem, tid, xt, hRow, g_wt0, nullptr, 1024, colbase,
                       0, 0, -1, 0, 0, 0, g_s[0], nullptr, hRow);
        grid_bar(tid);
        // Level 1: s1 (tanh), s2 (relu), both from s0
        do_level<2, 1>(smem, tid, g_s[0], nullptr, g_wts[0], g_wts[1], 512,
                       colbase, 0, 1, 0, 0, 1, 2, g_s[1], g_s[2], nullptr);
        grid_bar(tid);
        // Level 2: s3 (sigm), s4 (id) from s1; s5 (tanh), s6 (relu) from s2
        do_level<2, 1>(smem, tid, g_s[1], nullptr, g_wts[2], g_wts[3], 512,
                       colbase, 2, 3, 1, 1, 3, 4, g_s[3], g_s[4], nullptr);
        do_level<2, 1>(smem, tid, g_s[2], nullptr, g_wts[4], g_wts[5], 512,
                       colbase, 0, 1, 2, 2, 5, 6, nullptr, nullptr, nullptr);
        grid_bar(tid);
        // Level 3: s7 (sigm) from s3; s8 (id) from s4
        do_level<1, 1>(smem, tid, g_s[3], nullptr, g_wts[6], nullptr, 512,
                       colbase, 2, 0, 3, 0, 7, 0, nullptr, nullptr, nullptr);
        do_level<1, 1>(smem, tid, g_s[4], nullptr, g_wts[7], nullptr, 512,
                       colbase, 3, 0, 4, 0, 8, 0, nullptr, nullptr, nullptr);
        // h_new = mean(s1..s8)
        if (tid < 256) {
            const int b = tid >> 2, pj = tid & 3;
            float m = 0.f;
#pragma unroll
            for (int s2 = 1; s2 <= 8; ++s2) m += sl[s2 * 256 + b * 4 + pj];
            m *= 0.125f;
            out[(size_t)t * BB * HH + b * 512 + colbase + pj] = m;
            if (t == TT - 1 &&
                out_size >= (long long)TT * BB * HH + (long long)BB * HH)
                out[(size_t)TT * BB * HH + b * 512 + colbase + pj] = m;
        }
        grid_bar(tid);
    }
}

extern "C" void kernel_launch(void* const* d_in, const int* in_sizes, int n_in,
                              void* d_out, int out_size) {
    const float* x  = (const float*)d_in[0];
    const float* h0 = (const float*)d_in[1];
    const float* W0 = (const float*)d_in[2];
    const float* Ws = (const float*)d_in[3];
    float* out = (float*)d_out;

    dim3 tg(32, 32, 9), tb(32, 8);
    wt_transpose_kernel<<<tg, tb>>>(W0, Ws);

    cudaFuncSetAttribute(nao_kernel, cudaFuncAttributeMaxDynamicSharedMemorySize,
                         SMEM_TOTAL);
    nao_kernel<<<GRID, NTHREADS, SMEM_TOTAL>>>(x, h0, out, (long long)out_size);
}